// round 1
// baseline (speedup 1.0000x reference)
#include <cuda_runtime.h>

// Problem constants
#define N_   32
#define C_   64
#define T_   300
#define V_   25
#define O_   128
#define TO_  150
#define TV_  7500      // T_*V_
#define TOV_ 3750      // TO_*V_
#define KT_  9
#define KKT_ 1152      // O_*KT_

// Scratch (static device allocations — allowed)
__device__ float g_Asum[V_ * V_];
__device__ float g_agg [N_ * C_ * T_ * V_];          // 61.4 MB
__device__ float g_xgcn[N_ * O_ * T_ * V_];          // 122.9 MB
__device__ float g_xtcn[N_ * O_ * TO_ * V_];         // 61.4 MB
__device__ float g_scale[O_];
__device__ float g_shift[O_];

// ---------------------------------------------------------------------------
// K0: A_sum[v][w] = sum_p A_parts[p][v][w] * edge_importance[p]
// ---------------------------------------------------------------------------
__global__ void k_asum(const float* __restrict__ A_parts,
                       const float* __restrict__ ei) {
    int i = threadIdx.x;
    if (i < V_ * V_) {
        float s = 0.f;
        #pragma unroll
        for (int p = 0; p < 3; p++) s += A_parts[p * V_ * V_ + i] * ei[p];
        g_Asum[i] = s;
    }
}

// ---------------------------------------------------------------------------
// K1: agg[n,c,t,w] = sum_v x[n,c,t,v] * A_sum[v][w]
// one thread per output element; A_sum in smem
// ---------------------------------------------------------------------------
__global__ void __launch_bounds__(256) k_agg(const float* __restrict__ x) {
    __shared__ float As[V_ * V_];
    for (int i = threadIdx.x; i < V_ * V_; i += 256) As[i] = g_Asum[i];
    __syncthreads();
    int idx = blockIdx.x * 256 + threadIdx.x;
    int w = idx % V_;
    int row = idx / V_;
    const float* xr = x + (size_t)row * V_;
    float s = 0.f;
    #pragma unroll
    for (int v = 0; v < V_; v++) s += xr[v] * As[v * V_ + w];
    g_agg[idx] = s;
}

// ---------------------------------------------------------------------------
// K2: gcn — per-batch GEMM: out[o, s] = sum_c W[o,c]*agg_n[c, s] + b[o]
// M=128(O), K=64(C), N=7500.  Tiles: 128x128, full-K in smem (transposed, padded)
// 256 threads, 8x8 micro (4+4 split for float4 smem loads)
// ---------------------------------------------------------------------------
__global__ void __launch_bounds__(256) k_gcn(const float* __restrict__ W,
                                             const float* __restrict__ bias) {
    __shared__ float Wt[C_][132];    // [c][o], padded pitch
    __shared__ float Is[16][128];
    int tid = threadIdx.x;
    int n = blockIdx.y;
    int s0 = blockIdx.x * 128;
    const float* In = g_agg + (size_t)n * C_ * TV_;

    #pragma unroll
    for (int i = 0; i < 32; i++) {
        int e = i * 256 + tid;
        int c = e & 63, o = e >> 6;
        Wt[c][o] = W[o * C_ + c];    // coalesced global read
    }

    int tx = tid & 15, ty = tid >> 4;
    float acc[8][8] = {};

    for (int kt = 0; kt < 4; kt++) {
        __syncthreads();
        #pragma unroll
        for (int i = 0; i < 8; i++) {
            int e = i * 256 + tid;
            int sl = e & 127, cl = e >> 7;
            int s = s0 + sl;
            Is[cl][sl] = (s < TV_) ? In[(kt * 16 + cl) * TV_ + s] : 0.f;
        }
        __syncthreads();
        #pragma unroll
        for (int c = 0; c < 16; c++) {
            float4 a0 = *(const float4*)&Wt[kt * 16 + c][ty * 4];
            float4 a1 = *(const float4*)&Wt[kt * 16 + c][64 + ty * 4];
            float4 b0 = *(const float4*)&Is[c][tx * 4];
            float4 b1 = *(const float4*)&Is[c][64 + tx * 4];
            float a[8] = {a0.x, a0.y, a0.z, a0.w, a1.x, a1.y, a1.z, a1.w};
            float b[8] = {b0.x, b0.y, b0.z, b0.w, b1.x, b1.y, b1.z, b1.w};
            #pragma unroll
            for (int i = 0; i < 8; i++)
                #pragma unroll
                for (int j = 0; j < 8; j++)
                    acc[i][j] += a[i] * b[j];
        }
    }

    float* Out = g_xgcn + (size_t)n * O_ * TV_;
    #pragma unroll
    for (int i = 0; i < 8; i++) {
        int o = (i < 4) ? (ty * 4 + i) : (64 + ty * 4 + i - 4);
        float bo = __ldg(&bias[o]);
        #pragma unroll
        for (int j = 0; j < 8; j++) {
            int s = s0 + ((j < 4) ? (tx * 4 + j) : (64 + tx * 4 + j - 4));
            if (s < TV_) Out[o * TV_ + s] = acc[i][j] + bo;
        }
    }
}

// ---------------------------------------------------------------------------
// K3: tcn — implicit-im2col GEMM per batch:
//   out[o, s=(t,v)] = sum_{kk=(ci,k)} W[o,kk] * xgcn_n[ci, 2t+k-4, v] + b[o]
// M=128(O), K=1152, N=3750.  128x128x16 tiles, 8x8 micro.
// ---------------------------------------------------------------------------
__global__ void __launch_bounds__(256) k_tcn(const float* __restrict__ W,
                                             const float* __restrict__ bias) {
    __shared__ float Wt[16][132];    // [kk_l][o]
    __shared__ float Is[16][128];
    __shared__ int st2[128];
    __shared__ int sv[128];
    int tid = threadIdx.x;
    int n = blockIdx.y;
    int s0 = blockIdx.x * 128;
    const float* In = g_xgcn + (size_t)n * O_ * TV_;

    if (tid < 128) {
        int s = s0 + tid;
        if (s < TOV_) { st2[tid] = (s / V_) * 2; sv[tid] = s % V_; }
        else          { st2[tid] = -100000;      sv[tid] = 0; }
    }
    __syncthreads();

    int myS = tid & 127;
    int my_t2 = st2[myS];
    int my_v  = sv[myS];
    int kk_par = tid >> 7;   // 0 or 1
    int tx = tid & 15, ty = tid >> 4;
    float acc[8][8] = {};

    for (int kk0 = 0; kk0 < KKT_; kk0 += 16) {
        __syncthreads();
        // W tile: [kk_l][o]
        #pragma unroll
        for (int i = 0; i < 8; i++) {
            int e = i * 256 + tid;
            int kkl = e & 15, o = e >> 4;
            Wt[kkl][o] = W[o * KKT_ + kk0 + kkl];
        }
        // In tile (gather): thread's s is fixed, kk_l varies
        #pragma unroll
        for (int i = 0; i < 8; i++) {
            int kkl = 2 * i + kk_par;
            int kk = kk0 + kkl;
            int ci = kk / 9;
            int k  = kk - ci * 9;
            int tp = my_t2 + k - 4;
            float vload = 0.f;
            if ((unsigned)tp < (unsigned)T_)
                vload = In[(ci * T_ + tp) * V_ + my_v];
            Is[kkl][myS] = vload;
        }
        __syncthreads();
        #pragma unroll
        for (int c = 0; c < 16; c++) {
            float4 a0 = *(const float4*)&Wt[c][ty * 4];
            float4 a1 = *(const float4*)&Wt[c][64 + ty * 4];
            float4 b0 = *(const float4*)&Is[c][tx * 4];
            float4 b1 = *(const float4*)&Is[c][64 + tx * 4];
            float a[8] = {a0.x, a0.y, a0.z, a0.w, a1.x, a1.y, a1.z, a1.w};
            float b[8] = {b0.x, b0.y, b0.z, b0.w, b1.x, b1.y, b1.z, b1.w};
            #pragma unroll
            for (int i = 0; i < 8; i++)
                #pragma unroll
                for (int j = 0; j < 8; j++)
                    acc[i][j] += a[i] * b[j];
        }
    }

    float* Out = g_xtcn + (size_t)n * O_ * TOV_;
    #pragma unroll
    for (int i = 0; i < 8; i++) {
        int o = (i < 4) ? (ty * 4 + i) : (64 + ty * 4 + i - 4);
        float bo = __ldg(&bias[o]);
        #pragma unroll
        for (int j = 0; j < 8; j++) {
            int s = s0 + ((j < 4) ? (tx * 4 + j) : (64 + tx * 4 + j - 4));
            if (s < TOV_) Out[o * TOV_ + s] = acc[i][j] + bo;
        }
    }
}

// ---------------------------------------------------------------------------
// K4: BN stats — one block per channel o; double accumulation
// ---------------------------------------------------------------------------
__global__ void __launch_bounds__(256) k_stats(const float* __restrict__ gamma,
                                               const float* __restrict__ beta) {
    __shared__ double sh[512];
    int o = blockIdx.x;
    double s = 0.0, s2 = 0.0;
    for (int nn = 0; nn < N_; nn++) {
        const float* p = g_xtcn + ((size_t)nn * O_ + o) * TOV_;
        for (int i = threadIdx.x; i < TOV_; i += 256) {
            float v = p[i];
            s  += (double)v;
            s2 += (double)v * (double)v;
        }
    }
    sh[threadIdx.x] = s;
    sh[256 + threadIdx.x] = s2;
    __syncthreads();
    for (int st = 128; st > 0; st >>= 1) {
        if (threadIdx.x < st) {
            sh[threadIdx.x] += sh[threadIdx.x + st];
            sh[256 + threadIdx.x] += sh[256 + threadIdx.x + st];
        }
        __syncthreads();
    }
    if (threadIdx.x == 0) {
        double cnt = (double)N_ * (double)TOV_;
        double mean = sh[0] / cnt;
        double var = sh[256] / cnt - mean * mean;
        float rstd = (float)(1.0 / sqrt(var + 1e-5));
        float sc = gamma[o] * rstd;
        g_scale[o] = sc;
        g_shift[o] = beta[o] - (float)mean * sc;
    }
}

// ---------------------------------------------------------------------------
// K5: final — residual GEMM (K=64 over original x, strided t) fused with
//     BN affine + add + ReLU, writes d_out.
// ---------------------------------------------------------------------------
__global__ void __launch_bounds__(256) k_final(const float* __restrict__ x,
                                               const float* __restrict__ W,
                                               const float* __restrict__ bias,
                                               float* __restrict__ out) {
    __shared__ float Wt[C_][132];
    __shared__ float Is[16][128];
    __shared__ int st2[128];
    __shared__ int sv[128];
    int tid = threadIdx.x;
    int n = blockIdx.y;
    int s0 = blockIdx.x * 128;
    const float* In = x + (size_t)n * C_ * TV_;

    #pragma unroll
    for (int i = 0; i < 32; i++) {
        int e = i * 256 + tid;
        int c = e & 63, o = e >> 6;
        Wt[c][o] = W[o * C_ + c];
    }
    if (tid < 128) {
        int s = s0 + tid;
        if (s < TOV_) { st2[tid] = (s / V_) * 2; sv[tid] = s % V_; }
        else          { st2[tid] = 0;            sv[tid] = 0; }
    }
    __syncthreads();

    int myS = tid & 127;
    int my_t2 = st2[myS];
    int my_v  = sv[myS];
    int kk_par = tid >> 7;
    int tx = tid & 15, ty = tid >> 4;
    float acc[8][8] = {};

    for (int kt = 0; kt < 4; kt++) {
        __syncthreads();
        #pragma unroll
        for (int i = 0; i < 8; i++) {
            int cl = 2 * i + kk_par;
            int c = kt * 16 + cl;
            Is[cl][myS] = In[(c * T_ + my_t2) * V_ + my_v];
        }
        __syncthreads();
        #pragma unroll
        for (int c = 0; c < 16; c++) {
            float4 a0 = *(const float4*)&Wt[kt * 16 + c][ty * 4];
            float4 a1 = *(const float4*)&Wt[kt * 16 + c][64 + ty * 4];
            float4 b0 = *(const float4*)&Is[c][tx * 4];
            float4 b1 = *(const float4*)&Is[c][64 + tx * 4];
            float a[8] = {a0.x, a0.y, a0.z, a0.w, a1.x, a1.y, a1.z, a1.w};
            float b[8] = {b0.x, b0.y, b0.z, b0.w, b1.x, b1.y, b1.z, b1.w};
            #pragma unroll
            for (int i = 0; i < 8; i++)
                #pragma unroll
                for (int j = 0; j < 8; j++)
                    acc[i][j] += a[i] * b[j];
        }
    }

    const float* Tcn = g_xtcn + (size_t)n * O_ * TOV_;
    #pragma unroll
    for (int i = 0; i < 8; i++) {
        int o = (i < 4) ? (ty * 4 + i) : (64 + ty * 4 + i - 4);
        float bo = __ldg(&bias[o]);
        float sc = g_scale[o];
        float sh = g_shift[o];
        #pragma unroll
        for (int j = 0; j < 8; j++) {
            int s = s0 + ((j < 4) ? (tx * 4 + j) : (64 + tx * 4 + j - 4));
            if (s < TOV_) {
                float bn = Tcn[o * TOV_ + s] * sc + sh;
                float v = bn + acc[i][j] + bo;
                out[((size_t)n * O_ + o) * TOV_ + s] = fmaxf(v, 0.f);
            }
        }
    }
}

// ---------------------------------------------------------------------------
extern "C" void kernel_launch(void* const* d_in, const int* in_sizes, int n_in,
                              void* d_out, int out_size) {
    const float* x       = (const float*)d_in[0];
    const float* A_parts = (const float*)d_in[1];
    const float* ei      = (const float*)d_in[2];
    const float* gcn_w   = (const float*)d_in[3];
    const float* gcn_b   = (const float*)d_in[4];
    const float* tcn_w   = (const float*)d_in[5];
    const float* tcn_b   = (const float*)d_in[6];
    const float* bn_g    = (const float*)d_in[7];
    const float* bn_b    = (const float*)d_in[8];
    const float* res_w   = (const float*)d_in[9];
    const float* res_b   = (const float*)d_in[10];
    float* out = (float*)d_out;

    k_asum<<<1, 640>>>(A_parts, ei);
    k_agg<<<(N_ * C_ * T_ * V_) / 256, 256>>>(x);
    dim3 ggcn((TV_ + 127) / 128, N_);
    k_gcn<<<ggcn, 256>>>(gcn_w, gcn_b);
    dim3 gtcn((TOV_ + 127) / 128, N_);
    k_tcn<<<gtcn, 256>>>(tcn_w, tcn_b);
    k_stats<<<O_, 256>>>(bn_g, bn_b);
    dim3 gfin((TOV_ + 127) / 128, N_);
    k_final<<<gfin, 256>>>(x, res_w, res_b, out);
}

// round 2
// speedup vs baseline: 1.5170x; 1.5170x over previous
#include <cuda_runtime.h>

// Problem constants
#define N_   32
#define C_   64
#define T_   300
#define V_   25
#define O_   128
#define TO_  150
#define TV_  7500      // T_*V_
#define TOV_ 3750      // TO_*V_
#define KT_  9
#define KKE_ 576       // C_*KT_  (effective K after gcn/tcn fusion)

// Scratch (static device allocations — allowed)
__device__ float g_Asum[V_ * V_];
__device__ float g_agg [N_ * C_ * T_ * V_];          // 61.4 MB
__device__ float g_xtcn[N_ * O_ * TO_ * V_];         // 61.4 MB
__device__ float g_Weff[KKE_ * O_];                  // [kk=(c*9+k)][o]
__device__ float g_beff[O_ * TO_];                   // [o][t]
__device__ float g_scale[O_];
__device__ float g_shift[O_];

// ---------------------------------------------------------------------------
// K0: A_sum[v][w] = sum_p A_parts[p][v][w] * edge_importance[p]
// ---------------------------------------------------------------------------
__global__ void k_asum(const float* __restrict__ A_parts,
                       const float* __restrict__ ei) {
    int i = threadIdx.x;
    if (i < V_ * V_) {
        float s = 0.f;
        #pragma unroll
        for (int p = 0; p < 3; p++) s += A_parts[p * V_ * V_ + i] * ei[p];
        g_Asum[i] = s;
    }
}

// ---------------------------------------------------------------------------
// K1: agg[n,c,t,w] = sum_v x[n,c,t,v] * A_sum[v][w]
// ---------------------------------------------------------------------------
__global__ void __launch_bounds__(256) k_agg(const float* __restrict__ x) {
    __shared__ float As[V_ * V_];
    for (int i = threadIdx.x; i < V_ * V_; i += 256) As[i] = g_Asum[i];
    __syncthreads();
    int idx = blockIdx.x * 256 + threadIdx.x;
    int w = idx % V_;
    int row = idx / V_;
    const float* xr = x + (size_t)row * V_;
    float s = 0.f;
    #pragma unroll
    for (int v = 0; v < V_; v++) s += xr[v] * As[v * V_ + w];
    g_agg[idx] = s;
}

// ---------------------------------------------------------------------------
// K2a: W_eff[(c*9+k)][o] = sum_{o2} tcn_w[o,o2,k] * gcn_w[o2,c]
// grid = 576 blocks (one per (c,k)), 128 threads (o)
// ---------------------------------------------------------------------------
__global__ void __launch_bounds__(128) k_weff(const float* __restrict__ tcn_w,
                                              const float* __restrict__ gcn_w) {
    __shared__ float gc[O_];
    int ck = blockIdx.x;
    int c = ck / KT_, k = ck % KT_;
    int o = threadIdx.x;
    gc[o] = gcn_w[o * C_ + c];       // gcn_w is [128][64]; index = o2*64+c
    __syncthreads();
    const float* wrow = tcn_w + (size_t)o * O_ * KT_ + k;   // stride 9 over o2
    float s = 0.f;
    #pragma unroll 8
    for (int o2 = 0; o2 < O_; o2++) s += wrow[o2 * KT_] * gc[o2];
    g_Weff[ck * O_ + o] = s;
}

// ---------------------------------------------------------------------------
// K2b: bias_eff[o][t] = tcn_b[o] + sum_{valid k} sum_{o2} tcn_w[o,o2,k]*gcn_b[o2]
// one block, 128 threads
// ---------------------------------------------------------------------------
__global__ void __launch_bounds__(128) k_beff(const float* __restrict__ tcn_w,
                                              const float* __restrict__ gcn_b,
                                              const float* __restrict__ tcn_b) {
    int o = threadIdx.x;
    float B[KT_];
    #pragma unroll
    for (int k = 0; k < KT_; k++) {
        float s = 0.f;
        const float* wrow = tcn_w + (size_t)o * O_ * KT_ + k;
        for (int o2 = 0; o2 < O_; o2++) s += wrow[o2 * KT_] * gcn_b[o2];
        B[k] = s;
    }
    float tb = tcn_b[o];
    for (int t = 0; t < TO_; t++) {
        float s = tb;
        #pragma unroll
        for (int k = 0; k < KT_; k++) {
            int tp = 2 * t + k - 4;
            if (tp >= 0 && tp < T_) s += B[k];
        }
        g_beff[o * TO_ + t] = s;
    }
}

// ---------------------------------------------------------------------------
// K3: fused gcn+tcn — implicit-im2col GEMM per batch:
//   out[o, s=(t,v)] = sum_{kk=(c,k)} Weff[kk][o] * agg_n[c, 2t+k-4, v] + beff[o][t]
// M=128(O), K=576, N=3750.  128x128x16 tiles, 8x8 micro, double-buffered smem.
// ---------------------------------------------------------------------------
__global__ void __launch_bounds__(256, 2) k_tcn() {
    __shared__ float Wt[2][16][132];
    __shared__ float Is[2][16][128];
    int tid = threadIdx.x;
    int n = blockIdx.y;
    int s0 = blockIdx.x * 128;
    const float* In = g_agg + (size_t)n * C_ * TV_;

    int myS = tid & 127;
    int kk_par = tid >> 7;            // 0 or 1
    int s = s0 + myS;
    bool sval = s < TOV_;
    int my_t2 = sval ? (s / V_) * 2 : -100000;
    int my_v  = sval ? (s % V_) : 0;
    int tx = tid & 15, ty = tid >> 4;

    float wreg[8], ireg[8];
    float acc[8][8] = {};

    // prologue: load tile kt=0 into buf 0
    #pragma unroll
    for (int i = 0; i < 8; i++) {
        int kkl = 2 * i + kk_par;
        Wt[0][kkl][myS] = g_Weff[kkl * O_ + myS];
        int ci = kkl / KT_, k = kkl % KT_;
        int tp = my_t2 + k - 4;
        float vl = 0.f;
        if ((unsigned)tp < (unsigned)T_) vl = In[(ci * T_ + tp) * V_ + my_v];
        Is[0][kkl][myS] = vl;
    }
    __syncthreads();

    const int NKT = KKE_ / 16;   // 36
    for (int kt = 0; kt < NKT; kt++) {
        int cur = kt & 1;
        // prefetch next tile into registers
        if (kt + 1 < NKT) {
            int kk0 = (kt + 1) * 16;
            #pragma unroll
            for (int i = 0; i < 8; i++) {
                int kkl = 2 * i + kk_par;
                int kk = kk0 + kkl;
                wreg[i] = g_Weff[kk * O_ + myS];
                int ci = kk / KT_, k = kk - ci * KT_;
                int tp = my_t2 + k - 4;
                float vl = 0.f;
                if ((unsigned)tp < (unsigned)T_) vl = In[(ci * T_ + tp) * V_ + my_v];
                ireg[i] = vl;
            }
        }
        // compute on current buffer
        #pragma unroll
        for (int c = 0; c < 16; c++) {
            float4 a0 = *(const float4*)&Wt[cur][c][ty * 4];
            float4 a1 = *(const float4*)&Wt[cur][c][64 + ty * 4];
            float4 b0 = *(const float4*)&Is[cur][c][tx * 4];
            float4 b1 = *(const float4*)&Is[cur][c][64 + tx * 4];
            float a[8] = {a0.x, a0.y, a0.z, a0.w, a1.x, a1.y, a1.z, a1.w};
            float b[8] = {b0.x, b0.y, b0.z, b0.w, b1.x, b1.y, b1.z, b1.w};
            #pragma unroll
            for (int i = 0; i < 8; i++)
                #pragma unroll
                for (int j = 0; j < 8; j++)
                    acc[i][j] += a[i] * b[j];
        }
        // store prefetched tile into other buffer
        if (kt + 1 < NKT) {
            int nxt = cur ^ 1;
            #pragma unroll
            for (int i = 0; i < 8; i++) {
                int kkl = 2 * i + kk_par;
                Wt[nxt][kkl][myS] = wreg[i];
                Is[nxt][kkl][myS] = ireg[i];
            }
        }
        __syncthreads();
    }

    // epilogue: + bias_eff[o][t], write g_xtcn
    int sj[8], tj[8];
    #pragma unroll
    for (int j = 0; j < 8; j++) {
        int ss = s0 + ((j < 4) ? (tx * 4 + j) : (64 + tx * 4 + j - 4));
        sj[j] = ss;
        tj[j] = (ss < TOV_) ? ss / V_ : 0;
    }
    float* Out = g_xtcn + (size_t)n * O_ * TOV_;
    #pragma unroll
    for (int i = 0; i < 8; i++) {
        int o = (i < 4) ? (ty * 4 + i) : (64 + ty * 4 + i - 4);
        const float* be = g_beff + o * TO_;
        #pragma unroll
        for (int j = 0; j < 8; j++) {
            if (sj[j] < TOV_)
                Out[o * TOV_ + sj[j]] = acc[i][j] + be[tj[j]];
        }
    }
}

// ---------------------------------------------------------------------------
// K4: BN stats — one block per channel o; double accumulation
// ---------------------------------------------------------------------------
__global__ void __launch_bounds__(256) k_stats(const float* __restrict__ gamma,
                                               const float* __restrict__ beta) {
    __shared__ double sh[512];
    int o = blockIdx.x;
    double s = 0.0, s2 = 0.0;
    for (int nn = 0; nn < N_; nn++) {
        const float* p = g_xtcn + ((size_t)nn * O_ + o) * TOV_;
        for (int i = threadIdx.x; i < TOV_; i += 256) {
            float v = p[i];
            s  += (double)v;
            s2 += (double)v * (double)v;
        }
    }
    sh[threadIdx.x] = s;
    sh[256 + threadIdx.x] = s2;
    __syncthreads();
    for (int st = 128; st > 0; st >>= 1) {
        if (threadIdx.x < st) {
            sh[threadIdx.x] += sh[threadIdx.x + st];
            sh[256 + threadIdx.x] += sh[256 + threadIdx.x + st];
        }
        __syncthreads();
    }
    if (threadIdx.x == 0) {
        double cnt = (double)N_ * (double)TOV_;
        double mean = sh[0] / cnt;
        double var = sh[256] / cnt - mean * mean;
        float rstd = (float)(1.0 / sqrt(var + 1e-5));
        float sc = gamma[o] * rstd;
        g_scale[o] = sc;
        g_shift[o] = beta[o] - (float)mean * sc;
    }
}

// ---------------------------------------------------------------------------
// K5: final — residual GEMM (K=64 over original x, strided t) fused with
//     BN affine + add + ReLU, writes d_out.
// ---------------------------------------------------------------------------
__global__ void __launch_bounds__(256) k_final(const float* __restrict__ x,
                                               const float* __restrict__ W,
                                               const float* __restrict__ bias,
                                               float* __restrict__ out) {
    __shared__ float Wt[C_][132];
    __shared__ float Is[16][128];
    __shared__ int st2[128];
    __shared__ int sv[128];
    int tid = threadIdx.x;
    int n = blockIdx.y;
    int s0 = blockIdx.x * 128;
    const float* In = x + (size_t)n * C_ * TV_;

    #pragma unroll
    for (int i = 0; i < 32; i++) {
        int e = i * 256 + tid;
        int c = e & 63, o = e >> 6;
        Wt[c][o] = W[o * C_ + c];
    }
    if (tid < 128) {
        int s = s0 + tid;
        if (s < TOV_) { st2[tid] = (s / V_) * 2; sv[tid] = s % V_; }
        else          { st2[tid] = 0;            sv[tid] = 0; }
    }
    __syncthreads();

    int myS = tid & 127;
    int my_t2 = st2[myS];
    int my_v  = sv[myS];
    int kk_par = tid >> 7;
    int tx = tid & 15, ty = tid >> 4;
    float acc[8][8] = {};

    for (int kt = 0; kt < 4; kt++) {
        __syncthreads();
        #pragma unroll
        for (int i = 0; i < 8; i++) {
            int cl = 2 * i + kk_par;
            int c = kt * 16 + cl;
            Is[cl][myS] = In[(c * T_ + my_t2) * V_ + my_v];
        }
        __syncthreads();
        #pragma unroll
        for (int c = 0; c < 16; c++) {
            float4 a0 = *(const float4*)&Wt[kt * 16 + c][ty * 4];
            float4 a1 = *(const float4*)&Wt[kt * 16 + c][64 + ty * 4];
            float4 b0 = *(const float4*)&Is[c][tx * 4];
            float4 b1 = *(const float4*)&Is[c][64 + tx * 4];
            float a[8] = {a0.x, a0.y, a0.z, a0.w, a1.x, a1.y, a1.z, a1.w};
            float b[8] = {b0.x, b0.y, b0.z, b0.w, b1.x, b1.y, b1.z, b1.w};
            #pragma unroll
            for (int i = 0; i < 8; i++)
                #pragma unroll
                for (int j = 0; j < 8; j++)
                    acc[i][j] += a[i] * b[j];
        }
    }

    const float* Tcn = g_xtcn + (size_t)n * O_ * TOV_;
    #pragma unroll
    for (int i = 0; i < 8; i++) {
        int o = (i < 4) ? (ty * 4 + i) : (64 + ty * 4 + i - 4);
        float bo = __ldg(&bias[o]);
        float sc = g_scale[o];
        float sh = g_shift[o];
        #pragma unroll
        for (int j = 0; j < 8; j++) {
            int s = s0 + ((j < 4) ? (tx * 4 + j) : (64 + tx * 4 + j - 4));
            if (s < TOV_) {
                float bn = Tcn[o * TOV_ + s] * sc + sh;
                float v = bn + acc[i][j] + bo;
                out[((size_t)n * O_ + o) * TOV_ + s] = fmaxf(v, 0.f);
            }
        }
    }
}

// ---------------------------------------------------------------------------
extern "C" void kernel_launch(void* const* d_in, const int* in_sizes, int n_in,
                              void* d_out, int out_size) {
    const float* x       = (const float*)d_in[0];
    const float* A_parts = (const float*)d_in[1];
    const float* ei      = (const float*)d_in[2];
    const float* gcn_w   = (const float*)d_in[3];
    const float* gcn_b   = (const float*)d_in[4];
    const float* tcn_w   = (const float*)d_in[5];
    const float* tcn_b   = (const float*)d_in[6];
    const float* bn_g    = (const float*)d_in[7];
    const float* bn_b    = (const float*)d_in[8];
    const float* res_w   = (const float*)d_in[9];
    const float* res_b   = (const float*)d_in[10];
    float* out = (float*)d_out;

    k_asum<<<1, 640>>>(A_parts, ei);
    k_agg<<<(N_ * C_ * T_ * V_) / 256, 256>>>(x);
    k_weff<<<KKE_, 128>>>(tcn_w, gcn_w);
    k_beff<<<1, 128>>>(tcn_w, gcn_b, tcn_b);
    dim3 gtcn((TOV_ + 127) / 128, N_);
    k_tcn<<<gtcn, 256>>>();
    k_stats<<<O_, 256>>>(bn_g, bn_b);
    dim3 gfin((TOV_ + 127) / 128, N_);
    k_final<<<gfin, 256>>>(x, res_w, res_b, out);
}